// round 15
// baseline (speedup 1.0000x reference)
#include <cuda_runtime.h>
#include <cuda_fp16.h>
#include <cstdint>

#define T_SEQ  2048
#define NB     4
#define NH     12
#define DH     64
#define DMODEL 768

#define N_X  (NB * T_SEQ * DMODEL)
#define N_WQ (3 * DMODEL * DMODEL)
#define N_WP (DMODEL * DMODEL)

// Scratch (device globals — no runtime allocation allowed)
__device__ __half g_q[NB * NH * T_SEQ * DH];      // [B][H][T][Dh], q scaled 0.125*log2e
__device__ __half g_k[NB * NH * T_SEQ * DH];      // [B][H][T][Dh]
__device__ __half g_v[NB * NH * T_SEQ * DH];      // [B][H][Dh][T] TRANSPOSED
__device__ __half g_attn[NB * T_SEQ * DMODEL];    // attention out (proj A operand)
__device__ __half g_xh[N_X];                      // fp16 X
__device__ __half g_wqh[N_WQ];                    // fp16 W_qkv
__device__ __half g_wph[N_WP];                    // fp16 W_proj

__device__ __forceinline__ uint2 f4_to_h4(float4 v) {
    __half2 lo = __float22half2_rn(make_float2(v.x, v.y));
    __half2 hi = __float22half2_rn(make_float2(v.z, v.w));
    uint2 r;
    r.x = *(uint32_t*)&lo;
    r.y = *(uint32_t*)&hi;
    return r;
}

__device__ __forceinline__ uint32_t f2_to_h2(float a, float b) {
    __half2 h = __float22half2_rn(make_float2(a, b));
    return *(uint32_t*)&h;
}

__device__ __forceinline__ float ex2(float x) {
    float r;
    asm("ex2.approx.f32 %0, %1;" : "=f"(r) : "f"(x));
    return r;
}

__device__ __forceinline__ void ldsm4(uint32_t (&r)[4], uint32_t addr) {
    asm volatile("ldmatrix.sync.aligned.m8n8.x4.shared.b16 {%0,%1,%2,%3}, [%4];\n"
                 : "=r"(r[0]), "=r"(r[1]), "=r"(r[2]), "=r"(r[3]) : "r"(addr));
}

__device__ __forceinline__ void mma16(float (&d)[4], const uint32_t (&a)[4],
                                      uint32_t b0, uint32_t b1) {
    asm volatile(
        "mma.sync.aligned.m16n8k16.row.col.f32.f16.f16.f32 "
        "{%0,%1,%2,%3}, {%4,%5,%6,%7}, {%8,%9}, {%0,%1,%2,%3};\n"
        : "+f"(d[0]), "+f"(d[1]), "+f"(d[2]), "+f"(d[3])
        : "r"(a[0]), "r"(a[1]), "r"(a[2]), "r"(a[3]), "r"(b0), "r"(b1));
}

#define CP16(dst_u32, src_ptr) \
    asm volatile("cp.async.cg.shared.global [%0], [%1], 16;\n" \
                 :: "r"(dst_u32), "l"(src_ptr) : "memory")
#define CP_COMMIT() asm volatile("cp.async.commit_group;\n" ::: "memory")
#define CP_WAIT_ALL() asm volatile("cp.async.wait_all;\n" ::: "memory")
#define CP_WAIT_1() asm volatile("cp.async.wait_group 1;\n" ::: "memory")

// ---------------------------------------------------------------------------
// Prep: fp32 -> fp16 conversion of X, W_qkv, W_proj (8 floats per thread).
// ---------------------------------------------------------------------------
__global__ void __launch_bounds__(256) prep_kernel(
    const float* __restrict__ x, const float* __restrict__ wq,
    const float* __restrict__ wp)
{
    size_t e = ((size_t)blockIdx.x * 256 + threadIdx.x) * 8;
    const size_t n1 = N_X, n2 = (size_t)N_X + N_WQ, n3 = (size_t)N_X + N_WQ + N_WP;
    if (e >= n3) return;
    const float* src;
    __half* dst;
    size_t off;
    if (e < n1)      { src = x;  dst = g_xh;  off = e; }
    else if (e < n2) { src = wq; dst = g_wqh; off = e - n1; }
    else             { src = wp; dst = g_wph; off = e - n2; }
    float4 v0 = *(const float4*)(src + off);
    float4 v1 = *(const float4*)(src + off + 4);
    uint4 o;
    uint2 a = f4_to_h4(v0), b = f4_to_h4(v1);
    o.x = a.x; o.y = a.y; o.z = b.x; o.w = b.y;
    *(uint4*)(dst + off) = o;
}

// ---------------------------------------------------------------------------
// All-fp16 GEMM core (R12/R14-proven): 128M x 64N, BK=64, 256 thr,
// m16n8k16 + ldmatrix + cp.async 2-buffer.
// ---------------------------------------------------------------------------
#define GSTRIDE 144                       // bytes per staged row
#define A_BYTES (128 * GSTRIDE)           // 18432
#define STAGE_BYTES (192 * GSTRIDE)       // 27648
#define LDC 72
#define GEMM_SMEM (2 * STAGE_BYTES)       // 55296

extern __shared__ __align__(16) float g_smem[];

__device__ __forceinline__ void gemm_issue(
    uint32_t stage_u, const __half* __restrict__ Ab, const __half* __restrict__ Bb,
    int kt, int K, int tid)
{
#pragma unroll
    for (int it = 0; it < 4; it++) {
        int e = tid + it * 256, r = e >> 3, cb = (e & 7) << 4;
        CP16(stage_u + r * GSTRIDE + cb, Ab + (size_t)r * K + kt + (cb >> 1));
    }
#pragma unroll
    for (int it = 0; it < 2; it++) {
        int e = tid + it * 256, r = e >> 3, cb = (e & 7) << 4;
        CP16(stage_u + A_BYTES + r * GSTRIDE + cb, Bb + (size_t)r * K + kt + (cb >> 1));
    }
}

__device__ __forceinline__ void gemm_compute_h(
    uint32_t a_base, uint32_t b_base, float (&acc)[2][4][4])
{
#pragma unroll
    for (int ks = 0; ks < 4; ks++) {
        uint32_t a0[4], a1[4];
        ldsm4(a0, a_base + ks * 32);
        ldsm4(a1, a_base + 16 * GSTRIDE + ks * 32);
#pragma unroll
        for (int np = 0; np < 2; np++) {
            uint32_t b[4];
            ldsm4(b, b_base + np * 16 * GSTRIDE + ks * 32);
            mma16(acc[0][np * 2],     a0, b[0], b[1]);
            mma16(acc[0][np * 2 + 1], a0, b[2], b[3]);
            mma16(acc[1][np * 2],     a1, b[0], b[1]);
            mma16(acc[1][np * 2 + 1], a1, b[2], b[3]);
        }
    }
}

__device__ __forceinline__ void gemm_core_hh(
    const __half* __restrict__ Ab, const __half* __restrict__ Bb, int K,
    float (&acc)[2][4][4], int tid, int wm, int wn)
{
    const int lane = tid & 31;
    uint32_t smem_u = (uint32_t)__cvta_generic_to_shared(g_smem);
    uint32_t a_base = smem_u + (wm + (lane & 15)) * GSTRIDE + ((lane >> 4) << 4);
    uint32_t b_base = smem_u + A_BYTES +
        (wn + ((lane >> 4) << 3) + (lane & 7)) * GSTRIDE + (((lane >> 3) & 1) << 4);

    const int NT = K / 64;   // 12
    gemm_issue(smem_u, Ab, Bb, 0, K, tid);
    CP_COMMIT();

#pragma unroll 1
    for (int i = 0; i < NT; i++) {
        int cur = i & 1;
        if (i + 1 < NT) {
            gemm_issue(smem_u + (cur ^ 1) * STAGE_BYTES, Ab, Bb, (i + 1) * 64, K, tid);
            CP_COMMIT();
            CP_WAIT_1();
        } else {
            CP_WAIT_ALL();
        }
        __syncthreads();
        gemm_compute_h(a_base + cur * STAGE_BYTES, b_base + cur * STAGE_BYTES, acc);
        __syncthreads();
    }
}

__device__ __forceinline__ void gemm_store_cs(
    float (&acc)[2][4][4], float* Cs, int lane, int wm, int wn)
{
    const int grp = lane >> 2, q4 = lane & 3;
#pragma unroll
    for (int mi = 0; mi < 2; mi++)
#pragma unroll
        for (int n8 = 0; n8 < 4; n8++)
#pragma unroll
            for (int hh = 0; hh < 2; hh++) {
                int row = wm + mi * 16 + grp + 8 * hh;
                int col = wn + n8 * 8 + 2 * q4;
                *(float2*)&Cs[row * LDC + col] =
                    make_float2(acc[mi][n8][2 * hh], acc[mi][n8][2 * hh + 1]);
            }
}

__global__ void __launch_bounds__(256) qkv_gemm_kernel(const float* __restrict__ bias)
{
    const int K = DMODEL;
    const int tid = threadIdx.x, lane = tid & 31, wid = tid >> 5;
    const int bn = blockIdx.x, bm = blockIdx.y;
    const int wm = (wid & 3) * 32, wn = (wid >> 2) * 32;

    float acc[2][4][4];
#pragma unroll
    for (int mi = 0; mi < 2; mi++)
#pragma unroll
        for (int n8 = 0; n8 < 4; n8++)
#pragma unroll
            for (int c = 0; c < 4; c++) acc[mi][n8][c] = 0.f;

    gemm_core_hh(g_xh + (size_t)bm * 128 * K, g_wqh + (size_t)bn * 64 * K, K,
                 acc, tid, wm, wn);
    __syncthreads();

    float* Cs = g_smem;
    gemm_store_cs(acc, Cs, lane, wm, wn);
    __syncthreads();

    const int nbase = bn * 64;
    const int which = nbase / DMODEL;
    const int hh = (nbase % DMODEL) / DH;

    if (which == 2) {
        // V: bias + TRANSPOSED fp16 store [b][h][d][t], coalesced along t.
#pragma unroll
        for (int it = 0; it < 8; it++) {
            int e = tid + it * 256;          // 2048 = 64 d x 32 t-chunks
            int d = e >> 5;                  // 0..63 (warp-uniform)
            int tb = (e & 31) << 2;          // 0..124
            int m = bm * 128 + tb;
            int b = m >> 11, t = m & (T_SEQ - 1);
            float bd = bias[nbase + d];
            __half hv[4];
#pragma unroll
            for (int j = 0; j < 4; j++) {
                int jj = (j + (tid & 3)) & 3;
                hv[jj] = __float2half_rn(Cs[(tb + jj) * LDC + d] + bd);
            }
            *(uint2*)(g_v + ((size_t)(b * NH + hh) * DH + d) * T_SEQ + t) =
                *(uint2*)hv;
        }
    } else {
        __half* dst = (which == 0) ? g_q : g_k;
        // Q scale folds softmax's log2(e): exp(s) computed as exp2(s') with
        // s' = q'·k, q' = q * 0.125 * log2(e).
        const float qscale = (which == 0) ? 0.125f * 1.44269504088896341f : 1.0f;
#pragma unroll
        for (int it = 0; it < 8; it++) {
            int e = tid + it * 256;
            int r = e >> 4, c = (e & 15) << 2;
            int m = bm * 128 + r;
            int b = m >> 11, t = m & (T_SEQ - 1);
            float4 v = *(float4*)&Cs[r * LDC + c];
            v.x = (v.x + bias[nbase + c]) * qscale;
            v.y = (v.y + bias[nbase + c + 1]) * qscale;
            v.z = (v.z + bias[nbase + c + 2]) * qscale;
            v.w = (v.w + bias[nbase + c + 3]) * qscale;
            __half* drow = dst + (((size_t)(b * NH + hh)) * T_SEQ + t) * DH;
            *(uint2*)&drow[c] = f4_to_h4(v);
        }
    }
}

__global__ void __launch_bounds__(256) proj_gemm_kernel(
    const float* __restrict__ bias, float* __restrict__ out)
{
    const int K = DMODEL;
    const int tid = threadIdx.x, lane = tid & 31, wid = tid >> 5;
    const int bn = blockIdx.x, bm = blockIdx.y;
    const int wm = (wid & 3) * 32, wn = (wid >> 2) * 32;

    float acc[2][4][4];
#pragma unroll
    for (int mi = 0; mi < 2; mi++)
#pragma unroll
        for (int n8 = 0; n8 < 4; n8++)
#pragma unroll
            for (int c = 0; c < 4; c++) acc[mi][n8][c] = 0.f;

    gemm_core_hh(g_attn + (size_t)bm * 128 * K, g_wph + (size_t)bn * 64 * K, K,
                 acc, tid, wm, wn);
    __syncthreads();

    float* Cs = g_smem;
    gemm_store_cs(acc, Cs, lane, wm, wn);
    __syncthreads();

    const int nbase = bn * 64;
#pragma unroll
    for (int it = 0; it < 8; it++) {
        int e = tid + it * 256;
        int r = e >> 4, c = (e & 15) << 2;
        int m = bm * 128 + r;
        float4 v = *(float4*)&Cs[r * LDC + c];
        v.x += bias[nbase + c];     v.y += bias[nbase + c + 1];
        v.z += bias[nbase + c + 2]; v.w += bias[nbase + c + 3];
        *(float4*)&out[(size_t)m * DMODEL + nbase + c] = v;
    }
}

// ---------------------------------------------------------------------------
// Flash attention fp16 (R12 shape) with shortened per-tile serial chain:
// exp via raw ex2 (log2e folded into Q), deferred l-reduction (single quad
// reduction at the end), Q-fragment load hoisted out of the loop.
// ---------------------------------------------------------------------------
#define ASTRIDE 144
#define TILE_B (64 * ASTRIDE)
#define OFF_Q  0
#define OFF_K0 (TILE_B)
#define OFF_K1 (2 * TILE_B)
#define OFF_V0 (3 * TILE_B)
#define OFF_V1 (4 * TILE_B)
#define ATTN_SMEM (5 * TILE_B)         // 46080 B

__global__ void __launch_bounds__(128) attn_kernel()
{
    const int tid = threadIdx.x;
    const int warp = tid >> 5, lane = tid & 31;
    const int grp = lane >> 2, q4 = lane & 3;
    const int wm = warp * 16;
    const int qt = blockIdx.x, h = blockIdx.y, b = blockIdx.z;

    const size_t bh = ((size_t)(b * NH + h)) * T_SEQ * DH;
    const __half* Qg = g_q + bh + (size_t)qt * 64 * DH;
    const __half* Kg = g_k + bh;
    const __half* Vtg = g_v + bh;   // [DH][T_SEQ]

    uint32_t smem_u = (uint32_t)__cvta_generic_to_shared(g_smem);
    const int sr = tid >> 3;
    const int scb = (tid & 7) << 4;
    const int sch = (tid & 7) << 3;

    const uint32_t a_pat = (wm + (lane & 15)) * ASTRIDE + ((lane >> 4) << 4);
    const uint32_t b_pat = (((lane >> 4) << 3) + (lane & 7)) * ASTRIDE +
                           (((lane >> 3) & 1) << 4);
    const uint32_t qa_base = smem_u + OFF_Q + a_pat;

#pragma unroll
    for (int it = 0; it < 4; it++) {
        int r = sr + it * 16;
        CP16(smem_u + OFF_Q + r * ASTRIDE + scb, Qg + (size_t)r * DH + sch);
        CP16(smem_u + OFF_K0 + r * ASTRIDE + scb, Kg + (size_t)r * DH + sch);
        CP16(smem_u + OFF_V0 + r * ASTRIDE + scb, Vtg + (size_t)r * T_SEQ + sch);
    }
    CP_COMMIT();

    float o[8][4];
#pragma unroll
    for (int j = 0; j < 8; j++)
#pragma unroll
        for (int c = 0; c < 4; c++) o[j][c] = 0.f;
    float l_lo = 0.f, l_hi = 0.f;   // lane-local partials; reduced at the end

    // ---- hoisted Q fragment load (tile 0 must have landed) ----
    uint32_t aq[4][4];
    CP_WAIT_ALL();
    __syncthreads();
#pragma unroll
    for (int ks = 0; ks < 4; ks++) ldsm4(aq[ks], qa_base + ks * 32);

    int buf = 0;
#pragma unroll 1
    for (int ti = 0; ti < T_SEQ / 64; ti++) {
        if (ti) {
            CP_WAIT_ALL();
            __syncthreads();
        }

        if (ti < T_SEQ / 64 - 1) {
            int kt = (ti + 1) * 64;
            int ko = (buf ^ 1) ? OFF_K1 : OFF_K0;
            int vo = (buf ^ 1) ? OFF_V1 : OFF_V0;
#pragma unroll
            for (int it = 0; it < 4; it++) {
                int r = sr + it * 16;
                CP16(smem_u + ko + r * ASTRIDE + scb, Kg + (size_t)(kt + r) * DH + sch);
                CP16(smem_u + vo + r * ASTRIDE + scb, Vtg + (size_t)r * T_SEQ + kt + sch);
            }
            CP_COMMIT();
        }

        const uint32_t kb_base = smem_u + (buf ? OFF_K1 : OFF_K0) + b_pat;
        const uint32_t vb_base = smem_u + (buf ? OFF_V1 : OFF_V0) + b_pat;

        // ---- S' = (Q*0.125*log2e) K^T ----
        float s[8][4];
#pragma unroll
        for (int j = 0; j < 8; j++)
#pragma unroll
            for (int c = 0; c < 4; c++) s[j][c] = 0.f;
#pragma unroll
        for (int ks = 0; ks < 4; ks++) {
#pragma unroll
            for (int np = 0; np < 4; np++) {
                uint32_t kb[4];
                ldsm4(kb, kb_base + np * 16 * ASTRIDE + ks * 32);
                mma16(s[np * 2], aq[ks], kb[0], kb[1]);
                mma16(s[np * 2 + 1], aq[ks], kb[2], kb[3]);
            }
        }

        // ---- softmax numerator: P = exp2(S') = exp(S); lane-local l ----
#pragma unroll
        for (int j = 0; j < 8; j++) {
            s[j][0] = ex2(s[j][0]);
            s[j][1] = ex2(s[j][1]);
            s[j][2] = ex2(s[j][2]);
            s[j][3] = ex2(s[j][3]);
            l_lo += s[j][0] + s[j][1];
            l_hi += s[j][2] + s[j][3];
        }

        // ---- O += P V : P packed from S accumulators in registers ----
#pragma unroll
        for (int ks = 0; ks < 4; ks++) {
            uint32_t ap[4];
            ap[0] = f2_to_h2(s[2 * ks][0],     s[2 * ks][1]);
            ap[1] = f2_to_h2(s[2 * ks][2],     s[2 * ks][3]);
            ap[2] = f2_to_h2(s[2 * ks + 1][0], s[2 * ks + 1][1]);
            ap[3] = f2_to_h2(s[2 * ks + 1][2], s[2 * ks + 1][3]);
#pragma unroll
            for (int np = 0; np < 4; np++) {
                uint32_t vb[4];
                ldsm4(vb, vb_base + np * 16 * ASTRIDE + ks * 32);
                mma16(o[np * 2], ap, vb[0], vb[1]);
                mma16(o[np * 2 + 1], ap, vb[2], vb[3]);
            }
        }
        buf ^= 1;
    }

    // ---- single deferred quad reduction of l ----
    l_lo += __shfl_xor_sync(0xffffffffu, l_lo, 1);
    l_lo += __shfl_xor_sync(0xffffffffu, l_lo, 2);
    l_hi += __shfl_xor_sync(0xffffffffu, l_hi, 1);
    l_hi += __shfl_xor_sync(0xffffffffu, l_hi, 2);

    float inv_lo = 1.f / l_lo, inv_hi = 1.f / l_hi;
    int t_lo = qt * 64 + wm + grp;
    __half* row_lo = g_attn + ((size_t)b * T_SEQ + t_lo) * DMODEL + h * DH;
    __half* row_hi = row_lo + 8 * DMODEL;
#pragma unroll
    for (int j = 0; j < 8; j++) {
        *(__half2*)(row_lo + j * 8 + 2 * q4) =
            __float22half2_rn(make_float2(o[j][0] * inv_lo, o[j][1] * inv_lo));
        *(__half2*)(row_hi + j * 8 + 2 * q4) =
            __float22half2_rn(make_float2(o[j][2] * inv_hi, o[j][3] * inv_hi));
    }
}

// ---------------------------------------------------------------------------
extern "C" void kernel_launch(void* const* d_in, const int* in_sizes, int n_in,
                              void* d_out, int out_size)
{
    const float* x      = (const float*)d_in[0];
    const float* W_qkv  = (const float*)d_in[1];
    const float* b_qkv  = (const float*)d_in[2];
    const float* W_proj = (const float*)d_in[3];
    const float* b_proj = (const float*)d_in[4];
    float* out = (float*)d_out;

    cudaFuncSetAttribute(qkv_gemm_kernel,
                         cudaFuncAttributeMaxDynamicSharedMemorySize, GEMM_SMEM);
    cudaFuncSetAttribute(proj_gemm_kernel,
                         cudaFuncAttributeMaxDynamicSharedMemorySize, GEMM_SMEM);
    cudaFuncSetAttribute(attn_kernel,
                         cudaFuncAttributeMaxDynamicSharedMemorySize, ATTN_SMEM);

    // 0) fp32 -> fp16 prep of X / W_qkv / W_proj
    {
        int n8 = (N_X + N_WQ + N_WP) / 8;
        prep_kernel<<<(n8 + 255) / 256, 256>>>(x, W_qkv, W_proj);
    }
    // 1) QKV GEMM + scatter (Q carries 0.125*log2e scale)
    {
        dim3 grid(3 * DMODEL / 64, (NB * T_SEQ) / 128);  // (36, 64)
        qkv_gemm_kernel<<<grid, 256, GEMM_SMEM>>>(b_qkv);
    }
    // 2) Flash attention
    {
        dim3 grid(T_SEQ / 64, NH, NB);  // (32, 12, 4)
        attn_kernel<<<grid, 128, ATTN_SMEM>>>();
    }
    // 3) Output projection
    {
        dim3 grid(DMODEL / 64, (NB * T_SEQ) / 128);  // (12, 64)
        proj_gemm_kernel<<<grid, 256, GEMM_SMEM>>>(b_proj, out);
    }
}

// round 16
// speedup vs baseline: 1.0520x; 1.0520x over previous
#include <cuda_runtime.h>
#include <cuda_fp16.h>
#include <cstdint>

#define T_SEQ  2048
#define NB     4
#define NH     12
#define DH     64
#define DMODEL 768

#define N_X  (NB * T_SEQ * DMODEL)
#define N_WQ (3 * DMODEL * DMODEL)
#define N_WP (DMODEL * DMODEL)

// Scratch (device globals — no runtime allocation allowed)
__device__ __half g_q[NB * NH * T_SEQ * DH];      // [B][H][T][Dh], q scaled 0.125*log2e
__device__ __half g_k[NB * NH * T_SEQ * DH];      // [B][H][T][Dh]
__device__ __half g_v[NB * NH * T_SEQ * DH];      // [B][H][Dh][T] TRANSPOSED
__device__ __half g_attn[NB * T_SEQ * DMODEL];    // attention out (proj A operand)
__device__ __half g_xh[N_X];                      // fp16 X
__device__ __half g_wqh[N_WQ];                    // fp16 W_qkv
__device__ __half g_wph[N_WP];                    // fp16 W_proj

__device__ __forceinline__ uint2 f4_to_h4(float4 v) {
    __half2 lo = __float22half2_rn(make_float2(v.x, v.y));
    __half2 hi = __float22half2_rn(make_float2(v.z, v.w));
    uint2 r;
    r.x = *(uint32_t*)&lo;
    r.y = *(uint32_t*)&hi;
    return r;
}

__device__ __forceinline__ uint32_t f2_to_h2(float a, float b) {
    __half2 h = __float22half2_rn(make_float2(a, b));
    return *(uint32_t*)&h;
}

__device__ __forceinline__ float ex2(float x) {
    float r;
    asm("ex2.approx.f32 %0, %1;" : "=f"(r) : "f"(x));
    return r;
}

__device__ __forceinline__ void ldsm4(uint32_t (&r)[4], uint32_t addr) {
    asm volatile("ldmatrix.sync.aligned.m8n8.x4.shared.b16 {%0,%1,%2,%3}, [%4];\n"
                 : "=r"(r[0]), "=r"(r[1]), "=r"(r[2]), "=r"(r[3]) : "r"(addr));
}

__device__ __forceinline__ void mma16(float (&d)[4], const uint32_t (&a)[4],
                                      uint32_t b0, uint32_t b1) {
    asm volatile(
        "mma.sync.aligned.m16n8k16.row.col.f32.f16.f16.f32 "
        "{%0,%1,%2,%3}, {%4,%5,%6,%7}, {%8,%9}, {%0,%1,%2,%3};\n"
        : "+f"(d[0]), "+f"(d[1]), "+f"(d[2]), "+f"(d[3])
        : "r"(a[0]), "r"(a[1]), "r"(a[2]), "r"(a[3]), "r"(b0), "r"(b1));
}

#define CP16(dst_u32, src_ptr) \
    asm volatile("cp.async.cg.shared.global [%0], [%1], 16;\n" \
                 :: "r"(dst_u32), "l"(src_ptr) : "memory")
#define CP_COMMIT() asm volatile("cp.async.commit_group;\n" ::: "memory")
#define CP_WAIT_ALL() asm volatile("cp.async.wait_all;\n" ::: "memory")
#define CP_WAIT_1() asm volatile("cp.async.wait_group 1;\n" ::: "memory")

// ---------------------------------------------------------------------------
// Prep: fp32 -> fp16 conversion of X, W_qkv, W_proj (8 floats per thread).
// ---------------------------------------------------------------------------
__global__ void __launch_bounds__(256) prep_kernel(
    const float* __restrict__ x, const float* __restrict__ wq,
    const float* __restrict__ wp)
{
    size_t e = ((size_t)blockIdx.x * 256 + threadIdx.x) * 8;
    const size_t n1 = N_X, n2 = (size_t)N_X + N_WQ, n3 = (size_t)N_X + N_WQ + N_WP;
    if (e >= n3) return;
    const float* src;
    __half* dst;
    size_t off;
    if (e < n1)      { src = x;  dst = g_xh;  off = e; }
    else if (e < n2) { src = wq; dst = g_wqh; off = e - n1; }
    else             { src = wp; dst = g_wph; off = e - n2; }
    float4 v0 = *(const float4*)(src + off);
    float4 v1 = *(const float4*)(src + off + 4);
    uint4 o;
    uint2 a = f4_to_h4(v0), b = f4_to_h4(v1);
    o.x = a.x; o.y = a.y; o.z = b.x; o.w = b.y;
    *(uint4*)(dst + off) = o;
}

// ---------------------------------------------------------------------------
// All-fp16 GEMM core (R12/R14-proven): 128M x 64N, BK=64, 256 thr,
// m16n8k16 + ldmatrix + cp.async 2-buffer.
// ---------------------------------------------------------------------------
#define GSTRIDE 144                       // bytes per staged row
#define A_BYTES (128 * GSTRIDE)           // 18432
#define STAGE_BYTES (192 * GSTRIDE)       // 27648
#define LDC 72
#define GEMM_SMEM (2 * STAGE_BYTES)       // 55296

extern __shared__ __align__(16) float g_smem[];

__device__ __forceinline__ void gemm_issue(
    uint32_t stage_u, const __half* __restrict__ Ab, const __half* __restrict__ Bb,
    int kt, int K, int tid)
{
#pragma unroll
    for (int it = 0; it < 4; it++) {
        int e = tid + it * 256, r = e >> 3, cb = (e & 7) << 4;
        CP16(stage_u + r * GSTRIDE + cb, Ab + (size_t)r * K + kt + (cb >> 1));
    }
#pragma unroll
    for (int it = 0; it < 2; it++) {
        int e = tid + it * 256, r = e >> 3, cb = (e & 7) << 4;
        CP16(stage_u + A_BYTES + r * GSTRIDE + cb, Bb + (size_t)r * K + kt + (cb >> 1));
    }
}

__device__ __forceinline__ void gemm_compute_h(
    uint32_t a_base, uint32_t b_base, float (&acc)[2][4][4])
{
#pragma unroll
    for (int ks = 0; ks < 4; ks++) {
        uint32_t a0[4], a1[4];
        ldsm4(a0, a_base + ks * 32);
        ldsm4(a1, a_base + 16 * GSTRIDE + ks * 32);
#pragma unroll
        for (int np = 0; np < 2; np++) {
            uint32_t b[4];
            ldsm4(b, b_base + np * 16 * GSTRIDE + ks * 32);
            mma16(acc[0][np * 2],     a0, b[0], b[1]);
            mma16(acc[0][np * 2 + 1], a0, b[2], b[3]);
            mma16(acc[1][np * 2],     a1, b[0], b[1]);
            mma16(acc[1][np * 2 + 1], a1, b[2], b[3]);
        }
    }
}

__device__ __forceinline__ void gemm_core_hh(
    const __half* __restrict__ Ab, const __half* __restrict__ Bb, int K,
    float (&acc)[2][4][4], int tid, int wm, int wn)
{
    const int lane = tid & 31;
    uint32_t smem_u = (uint32_t)__cvta_generic_to_shared(g_smem);
    uint32_t a_base = smem_u + (wm + (lane & 15)) * GSTRIDE + ((lane >> 4) << 4);
    uint32_t b_base = smem_u + A_BYTES +
        (wn + ((lane >> 4) << 3) + (lane & 7)) * GSTRIDE + (((lane >> 3) & 1) << 4);

    const int NT = K / 64;   // 12
    gemm_issue(smem_u, Ab, Bb, 0, K, tid);
    CP_COMMIT();

#pragma unroll 1
    for (int i = 0; i < NT; i++) {
        int cur = i & 1;
        if (i + 1 < NT) {
            gemm_issue(smem_u + (cur ^ 1) * STAGE_BYTES, Ab, Bb, (i + 1) * 64, K, tid);
            CP_COMMIT();
            CP_WAIT_1();
        } else {
            CP_WAIT_ALL();
        }
        __syncthreads();
        gemm_compute_h(a_base + cur * STAGE_BYTES, b_base + cur * STAGE_BYTES, acc);
        __syncthreads();
    }
}

__device__ __forceinline__ void gemm_store_cs(
    float (&acc)[2][4][4], float* Cs, int lane, int wm, int wn)
{
    const int grp = lane >> 2, q4 = lane & 3;
#pragma unroll
    for (int mi = 0; mi < 2; mi++)
#pragma unroll
        for (int n8 = 0; n8 < 4; n8++)
#pragma unroll
            for (int hh = 0; hh < 2; hh++) {
                int row = wm + mi * 16 + grp + 8 * hh;
                int col = wn + n8 * 8 + 2 * q4;
                *(float2*)&Cs[row * LDC + col] =
                    make_float2(acc[mi][n8][2 * hh], acc[mi][n8][2 * hh + 1]);
            }
}

__global__ void __launch_bounds__(256) qkv_gemm_kernel(const float* __restrict__ bias)
{
    const int K = DMODEL;
    const int tid = threadIdx.x, lane = tid & 31, wid = tid >> 5;
    const int bn = blockIdx.x, bm = blockIdx.y;
    const int wm = (wid & 3) * 32, wn = (wid >> 2) * 32;

    float acc[2][4][4];
#pragma unroll
    for (int mi = 0; mi < 2; mi++)
#pragma unroll
        for (int n8 = 0; n8 < 4; n8++)
#pragma unroll
            for (int c = 0; c < 4; c++) acc[mi][n8][c] = 0.f;

    gemm_core_hh(g_xh + (size_t)bm * 128 * K, g_wqh + (size_t)bn * 64 * K, K,
                 acc, tid, wm, wn);
    __syncthreads();

    float* Cs = g_smem;
    gemm_store_cs(acc, Cs, lane, wm, wn);
    __syncthreads();

    const int nbase = bn * 64;
    const int which = nbase / DMODEL;
    const int hh = (nbase % DMODEL) / DH;

    if (which == 2) {
        // V: bias + TRANSPOSED fp16 store [b][h][d][t], coalesced along t.
#pragma unroll
        for (int it = 0; it < 8; it++) {
            int e = tid + it * 256;          // 2048 = 64 d x 32 t-chunks
            int d = e >> 5;                  // 0..63 (warp-uniform)
            int tb = (e & 31) << 2;          // 0..124
            int m = bm * 128 + tb;
            int b = m >> 11, t = m & (T_SEQ - 1);
            float bd = bias[nbase + d];
            __half hv[4];
#pragma unroll
            for (int j = 0; j < 4; j++) {
                int jj = (j + (tid & 3)) & 3;
                hv[jj] = __float2half_rn(Cs[(tb + jj) * LDC + d] + bd);
            }
            *(uint2*)(g_v + ((size_t)(b * NH + hh) * DH + d) * T_SEQ + t) =
                *(uint2*)hv;
        }
    } else {
        __half* dst = (which == 0) ? g_q : g_k;
        // Q scale folds softmax's log2(e): exp(s) = exp2(q'·k) with
        // q' = q * 0.125 * log2(e).
        const float qscale = (which == 0) ? 0.125f * 1.44269504088896341f : 1.0f;
#pragma unroll
        for (int it = 0; it < 8; it++) {
            int e = tid + it * 256;
            int r = e >> 4, c = (e & 15) << 2;
            int m = bm * 128 + r;
            int b = m >> 11, t = m & (T_SEQ - 1);
            float4 v = *(float4*)&Cs[r * LDC + c];
            v.x = (v.x + bias[nbase + c]) * qscale;
            v.y = (v.y + bias[nbase + c + 1]) * qscale;
            v.z = (v.z + bias[nbase + c + 2]) * qscale;
            v.w = (v.w + bias[nbase + c + 3]) * qscale;
            __half* drow = dst + (((size_t)(b * NH + hh)) * T_SEQ + t) * DH;
            *(uint2*)&drow[c] = f4_to_h4(v);
        }
    }
}

__global__ void __launch_bounds__(256) proj_gemm_kernel(
    const float* __restrict__ bias, float* __restrict__ out)
{
    const int K = DMODEL;
    const int tid = threadIdx.x, lane = tid & 31, wid = tid >> 5;
    const int bn = blockIdx.x, bm = blockIdx.y;
    const int wm = (wid & 3) * 32, wn = (wid >> 2) * 32;

    float acc[2][4][4];
#pragma unroll
    for (int mi = 0; mi < 2; mi++)
#pragma unroll
        for (int n8 = 0; n8 < 4; n8++)
#pragma unroll
            for (int c = 0; c < 4; c++) acc[mi][n8][c] = 0.f;

    gemm_core_hh(g_attn + (size_t)bm * 128 * K, g_wph + (size_t)bn * 64 * K, K,
                 acc, tid, wm, wn);
    __syncthreads();

    float* Cs = g_smem;
    gemm_store_cs(acc, Cs, lane, wm, wn);
    __syncthreads();

    const int nbase = bn * 64;
#pragma unroll
    for (int it = 0; it < 8; it++) {
        int e = tid + it * 256;
        int r = e >> 4, c = (e & 15) << 2;
        int m = bm * 128 + r;
        float4 v = *(float4*)&Cs[r * LDC + c];
        v.x += bias[nbase + c];     v.y += bias[nbase + c + 1];
        v.z += bias[nbase + c + 2]; v.w += bias[nbase + c + 3];
        *(float4*)&out[(size_t)m * DMODEL + nbase + c] = v;
    }
}

// ---------------------------------------------------------------------------
// Flash attention fp16 — EXACT R14 structure (64 q-rows, 128 thr = 4 warps,
// hoisted Q frags inside loop at ti==0, per-tile quad l-reduction,
// register-resident P). Single change vs R14: exp via raw ex2 (log2e is
// folded into the Q scale in the qkv epilogue).
// ---------------------------------------------------------------------------
#define ASTRIDE 144
#define TILE_B (64 * ASTRIDE)
#define OFF_Q  0
#define OFF_K0 (TILE_B)
#define OFF_K1 (2 * TILE_B)
#define OFF_V0 (3 * TILE_B)
#define OFF_V1 (4 * TILE_B)
#define ATTN_SMEM (5 * TILE_B)         // 46080 B

__global__ void __launch_bounds__(128) attn_kernel()
{
    const int tid = threadIdx.x;
    const int warp = tid >> 5, lane = tid & 31;
    const int grp = lane >> 2, q4 = lane & 3;
    const int wm = warp * 16;
    const int qt = blockIdx.x, h = blockIdx.y, b = blockIdx.z;

    const size_t bh = ((size_t)(b * NH + h)) * T_SEQ * DH;
    const __half* Qg = g_q + bh + (size_t)qt * 64 * DH;
    const __half* Kg = g_k + bh;
    const __half* Vtg = g_v + bh;   // [DH][T_SEQ]

    uint32_t smem_u = (uint32_t)__cvta_generic_to_shared(g_smem);
    const int sr = tid >> 3;
    const int scb = (tid & 7) << 4;
    const int sch = (tid & 7) << 3;

    const uint32_t a_pat = (wm + (lane & 15)) * ASTRIDE + ((lane >> 4) << 4);
    const uint32_t b_pat = (((lane >> 4) << 3) + (lane & 7)) * ASTRIDE +
                           (((lane >> 3) & 1) << 4);
    const uint32_t qa_base = smem_u + OFF_Q + a_pat;

#pragma unroll
    for (int it = 0; it < 4; it++) {
        int r = sr + it * 16;
        CP16(smem_u + OFF_Q + r * ASTRIDE + scb, Qg + (size_t)r * DH + sch);
        CP16(smem_u + OFF_K0 + r * ASTRIDE + scb, Kg + (size_t)r * DH + sch);
        CP16(smem_u + OFF_V0 + r * ASTRIDE + scb, Vtg + (size_t)r * T_SEQ + sch);
    }
    CP_COMMIT();

    float o[8][4];
#pragma unroll
    for (int j = 0; j < 8; j++)
#pragma unroll
        for (int c = 0; c < 4; c++) o[j][c] = 0.f;
    float l_lo = 0.f, l_hi = 0.f;

    uint32_t aq[4][4];
    int buf = 0;
#pragma unroll 1
    for (int ti = 0; ti < T_SEQ / 64; ti++) {
        CP_WAIT_ALL();
        __syncthreads();

        if (ti == 0) {
#pragma unroll
            for (int ks = 0; ks < 4; ks++) ldsm4(aq[ks], qa_base + ks * 32);
        }

        if (ti < T_SEQ / 64 - 1) {
            int kt = (ti + 1) * 64;
            int ko = (buf ^ 1) ? OFF_K1 : OFF_K0;
            int vo = (buf ^ 1) ? OFF_V1 : OFF_V0;
#pragma unroll
            for (int it = 0; it < 4; it++) {
                int r = sr + it * 16;
                CP16(smem_u + ko + r * ASTRIDE + scb, Kg + (size_t)(kt + r) * DH + sch);
                CP16(smem_u + vo + r * ASTRIDE + scb, Vtg + (size_t)r * T_SEQ + kt + sch);
            }
            CP_COMMIT();
        }

        const uint32_t kb_base = smem_u + (buf ? OFF_K1 : OFF_K0) + b_pat;
        const uint32_t vb_base = smem_u + (buf ? OFF_V1 : OFF_V0) + b_pat;

        // ---- S' = (Q*0.125*log2e) K^T ----
        float s[8][4];
#pragma unroll
        for (int j = 0; j < 8; j++)
#pragma unroll
            for (int c = 0; c < 4; c++) s[j][c] = 0.f;
#pragma unroll
        for (int ks = 0; ks < 4; ks++) {
#pragma unroll
            for (int np = 0; np < 4; np++) {
                uint32_t kb[4];
                ldsm4(kb, kb_base + np * 16 * ASTRIDE + ks * 32);
                mma16(s[np * 2], aq[ks], kb[0], kb[1]);
                mma16(s[np * 2 + 1], aq[ks], kb[2], kb[3]);
            }
        }

        // ---- softmax: P = exp2(S') = exp(S); per-tile quad l-reduction ----
        float rs_lo = 0.f, rs_hi = 0.f;
#pragma unroll
        for (int j = 0; j < 8; j++) {
            s[j][0] = ex2(s[j][0]);
            s[j][1] = ex2(s[j][1]);
            s[j][2] = ex2(s[j][2]);
            s[j][3] = ex2(s[j][3]);
            rs_lo += s[j][0] + s[j][1];
            rs_hi += s[j][2] + s[j][3];
        }
        rs_lo += __shfl_xor_sync(0xffffffffu, rs_lo, 1);
        rs_lo += __shfl_xor_sync(0xffffffffu, rs_lo, 2);
        rs_hi += __shfl_xor_sync(0xffffffffu, rs_hi, 1);
        rs_hi += __shfl_xor_sync(0xffffffffu, rs_hi, 2);
        l_lo += rs_lo;
        l_hi += rs_hi;

        // ---- O += P V : P packed from S accumulators in registers ----
#pragma unroll
        for (int ks = 0; ks < 4; ks++) {
            uint32_t ap[4];
            ap[0] = f2_to_h2(s[2 * ks][0],     s[2 * ks][1]);
            ap[1] = f2_to_h2(s[2 * ks][2],     s[2 * ks][3]);
            ap[2] = f2_to_h2(s[2 * ks + 1][0], s[2 * ks + 1][1]);
            ap[3] = f2_to_h2(s[2 * ks + 1][2], s[2 * ks + 1][3]);
#pragma unroll
            for (int np = 0; np < 4; np++) {
                uint32_t vb[4];
                ldsm4(vb, vb_base + np * 16 * ASTRIDE + ks * 32);
                mma16(o[np * 2], ap, vb[0], vb[1]);
                mma16(o[np * 2 + 1], ap, vb[2], vb[3]);
            }
        }
        buf ^= 1;
    }

    float inv_lo = 1.f / l_lo, inv_hi = 1.f / l_hi;
    int t_lo = qt * 64 + wm + grp;
    __half* row_lo = g_attn + ((size_t)b * T_SEQ + t_lo) * DMODEL + h * DH;
    __half* row_hi = row_lo + 8 * DMODEL;
#pragma unroll
    for (int j = 0; j < 8; j++) {
        *(__half2*)(row_lo + j * 8 + 2 * q4) =
            __float22half2_rn(make_float2(o[j][0] * inv_lo, o[j][1] * inv_lo));
        *(__half2*)(row_hi + j * 8 + 2 * q4) =
            __float22half2_rn(make_float2(o[j][2] * inv_hi, o[j][3] * inv_hi));
    }
}

// ---------------------------------------------------------------------------
extern "C" void kernel_launch(void* const* d_in, const int* in_sizes, int n_in,
                              void* d_out, int out_size)
{
    const float* x      = (const float*)d_in[0];
    const float* W_qkv  = (const float*)d_in[1];
    const float* b_qkv  = (const float*)d_in[2];
    const float* W_proj = (const float*)d_in[3];
    const float* b_proj = (const float*)d_in[4];
    float* out = (float*)d_out;

    cudaFuncSetAttribute(qkv_gemm_kernel,
                         cudaFuncAttributeMaxDynamicSharedMemorySize, GEMM_SMEM);
    cudaFuncSetAttribute(proj_gemm_kernel,
                         cudaFuncAttributeMaxDynamicSharedMemorySize, GEMM_SMEM);
    cudaFuncSetAttribute(attn_kernel,
                         cudaFuncAttributeMaxDynamicSharedMemorySize, ATTN_SMEM);

    // 0) fp32 -> fp16 prep of X / W_qkv / W_proj
    {
        int n8 = (N_X + N_WQ + N_WP) / 8;
        prep_kernel<<<(n8 + 255) / 256, 256>>>(x, W_qkv, W_proj);
    }
    // 1) QKV GEMM + scatter (Q carries 0.125*log2e scale)
    {
        dim3 grid(3 * DMODEL / 64, (NB * T_SEQ) / 128);  // (36, 64)
        qkv_gemm_kernel<<<grid, 256, GEMM_SMEM>>>(b_qkv);
    }
    // 2) Flash attention (R14 structure + ex2)
    {
        dim3 grid(T_SEQ / 64, NH, NB);  // (32, 12, 4)
        attn_kernel<<<grid, 128, ATTN_SMEM>>>();
    }
    // 3) Output projection
    {
        dim3 grid(DMODEL / 64, (NB * T_SEQ) / 128);  // (12, 64)
        proj_gemm_kernel<<<grid, 256, GEMM_SMEM>>>(b_proj, out);
    }
}